// round 3
// baseline (speedup 1.0000x reference)
#include <cuda_runtime.h>

#define T_STEPS 16
#define BLK 512

using ull = unsigned long long;

union F2u { ull u; float2 f; };

__device__ __forceinline__ ull fma2(ull a, ull b, ull c) {
    ull d;
    asm("fma.rn.f32x2 %0, %1, %2, %3;" : "=l"(d) : "l"(a), "l"(b), "l"(c));
    return d;
}
__device__ __forceinline__ float hsum2(ull a, ull b) {
    F2u x, y; x.u = a; y.u = b;
    return (x.f.x + y.f.x) + (x.f.y + y.f.y);
}
__device__ __forceinline__ float hsum1(ull a) { F2u x; x.u = a; return x.f.x + x.f.y; }
__device__ __forceinline__ ull pack2(float a, float b) { F2u t; t.f = make_float2(a, b); return t.u; }

__device__ __forceinline__ float sigm(float x) {
    return __fdividef(1.0f, 1.0f + __expf(-x));
}
__device__ __forceinline__ float tanh_fast(float x) {
    float ax = fabsf(x);
    float e = __expf(-2.0f * ax);
    float t = __fdividef(1.0f - e, 1.0f + e);
    return copysignf(t, x);
}
__device__ __forceinline__ float softplus_(float x) {
    // stable: max(x,0) + log1p(exp(-|x|))
    return fmaxf(x, 0.0f) + log1pf(__expf(-fabsf(x)));
}

// shared-memory float offsets
#define OFF_WHH 0        // 12288  (192 x 64, row-major)
#define OFF_W1T 12288    // 2048   (transposed: [m*64+k])
#define OFF_WIH 14336    // 384    (192 x 2, row-major -> ull per row)
#define OFF_BIH 14720    // 192
#define OFF_BHH 14912    // 192
#define OFF_B1  15104    // 32
#define OFF_W2  15136    // 128    (32 x 4 row-major -> float4 per row)
#define OFF_B2  15264    // 4
#define WEIGHT_BYTES (15268 * 4)                 // 61072, 16B-aligned
#define SMEM_BYTES (WEIGHT_BYTES + 32 * BLK * 8) // + hbuf (ull[32][BLK]) = 192144

__global__ void __launch_bounds__(BLK)
flow_kernel(const float* __restrict__ x, const float* __restrict__ z,
            const float* __restrict__ W_ih, const float* __restrict__ W_hh,
            const float* __restrict__ b_ih, const float* __restrict__ b_hh,
            const float* __restrict__ W1, const float* __restrict__ b1,
            const float* __restrict__ W2, const float* __restrict__ b2,
            float* __restrict__ out, int Btot)
{
    extern __shared__ unsigned char smem_raw[];
    float* sw = (float*)smem_raw;
    const int tid = threadIdx.x;

    // ---- stage weights into shared ----
    for (int i = tid; i < 12288; i += BLK) sw[OFF_WHH + i] = W_hh[i];
    for (int i = tid; i < 2048; i += BLK) {         // transpose W1 (64x32) -> [m][k]
        int m = i >> 6, k = i & 63;
        sw[OFF_W1T + i] = W1[k * 32 + m];
    }
    for (int i = tid; i < 384; i += BLK) sw[OFF_WIH + i] = W_ih[i];
    for (int i = tid; i < 192; i += BLK) { sw[OFF_BIH + i] = b_ih[i]; sw[OFF_BHH + i] = b_hh[i]; }
    for (int i = tid; i < 128; i += BLK) sw[OFF_W2 + i] = W2[i];
    if (tid < 32) sw[OFF_B1 + tid] = b1[tid];
    if (tid < 4)  sw[OFF_B2 + tid] = b2[tid];
    __syncthreads();

    ull* hbuf = (ull*)(smem_raw + WEIGHT_BYTES);   // [32][BLK] per-thread h scratch

    const int b = blockIdx.x * BLK + tid;

    // h = z  (packed pairs in registers + smem scratch copy)
    ull h2[32];
    const ull* zz = (const ull*)(z + (size_t)b * 64);
    #pragma unroll
    for (int k = 0; k < 32; ++k) { h2[k] = zz[k]; hbuf[k * BLK + tid] = h2[k]; }

    const float* xb = x + (size_t)b * (T_STEPS * 2);
    float*       yb = out + (size_t)b * (T_STEPS * 2);

    const ulonglong2* whh2 = (const ulonglong2*)(sw + OFF_WHH);  // row j at j*16
    const ull*        wih2 = (const ull*)(sw + OFF_WIH);         // row j at j
    const float* bih = sw + OFF_BIH;
    const float* bhh = sw + OFF_BHH;
    const ulonglong2* w1t2 = (const ulonglong2*)(sw + OFF_W1T);  // row m at m*16
    const float4* w2v = (const float4*)(sw + OFF_W2);
    const float* b1s = sw + OFF_B1;
    const float* b2s = sw + OFF_B2;
    const float bb20 = b2s[0], bb21 = b2s[1], bb22 = b2s[2], bb23 = b2s[3];

    float yp0 = 0.f, yp1 = 0.f;     // y_{t-1}
    float p0 = 1.f, p1 = 1.f;       // running scale products

    #pragma unroll 1
    for (int t = 0; t < T_STEPS; ++t) {
        ull y2 = pack2(yp0, yp1);

        // ---- GRU: gh = h @ W_hh^T + b_hh, fused with gates ----
        #pragma unroll 2
        for (int j = 0; j < 64; ++j) {
            const ulonglong2* wr = whh2 + j * 16;
            const ulonglong2* wzp = wr + 1024;   // row 64+j
            const ulonglong2* wn = wr + 2048;    // row 128+j
            ull ar0 = 0, ar1 = 0, az0 = 0, az1 = 0, an0 = 0, an1 = 0;
            #pragma unroll
            for (int kk = 0; kk < 16; ++kk) {
                ulonglong2 wa = wr[kk];
                ar0 = fma2(h2[2 * kk], wa.x, ar0); ar1 = fma2(h2[2 * kk + 1], wa.y, ar1);
                ulonglong2 wb = wzp[kk];
                az0 = fma2(h2[2 * kk], wb.x, az0); az1 = fma2(h2[2 * kk + 1], wb.y, az1);
                ulonglong2 wc = wn[kk];
                an0 = fma2(h2[2 * kk], wc.x, an0); an1 = fma2(h2[2 * kk + 1], wc.y, an1);
            }
            float hr = hsum2(ar0, ar1) + bhh[j];
            float hz = hsum2(az0, az1) + bhh[64 + j];
            float hn = hsum2(an0, an1) + bhh[128 + j];
            float gr = hsum1(fma2(y2, wih2[j],       0ULL)) + bih[j];
            float gz = hsum1(fma2(y2, wih2[64 + j],  0ULL)) + bih[64 + j];
            float gn = hsum1(fma2(y2, wih2[128 + j], 0ULL)) + bih[128 + j];
            float r = sigm(gr + hr);
            float u = sigm(gz + hz);
            float n = tanh_fast(gn + r * hn);
            // in-place h update in smem scratch (slot j only touched at iter j)
            float* hs = (float*)(hbuf + (j >> 1) * BLK + tid);
            float hold = hs[j & 1];
            hs[j & 1] = n + u * (hold - n);
        }

        // reload h (now h_new) into registers
        #pragma unroll
        for (int k = 0; k < 32; ++k) h2[k] = hbuf[k * BLK + tid];

        // ---- MLP: ls = relu(h@W1 + b1) @ W2 + b2, hid accumulated on the fly ----
        float ls0 = bb20, ls1 = bb21, ls2 = bb22, ls3 = bb23;
        #pragma unroll 2
        for (int m = 0; m < 32; ++m) {
            const ulonglong2* wm = w1t2 + m * 16;
            ull a0 = 0, a1 = 0;
            #pragma unroll
            for (int kk = 0; kk < 16; ++kk) {
                ulonglong2 w = wm[kk];
                a0 = fma2(h2[2 * kk], w.x, a0);
                a1 = fma2(h2[2 * kk + 1], w.y, a1);
            }
            float hid = fmaxf(hsum2(a0, a1) + b1s[m], 0.0f);
            float4 wv = w2v[m];
            ls0 = fmaf(hid, wv.x, ls0);
            ls1 = fmaf(hid, wv.y, ls1);
            ls2 = fmaf(hid, wv.z, ls2);
            ls3 = fmaf(hid, wv.w, ls3);
        }

        float s0 = softplus_(ls2) + 0.001f;
        float s1 = softplus_(ls3) + 0.001f;
        float2 xt = ((const float2*)xb)[t];
        float y0 = yp0 + ls0 + s0 * xt.x;
        float y1 = yp1 + ls1 + s1 * xt.y;
        ((float2*)yb)[t] = make_float2(y0, y1);
        p0 *= s0; p1 *= s1;
        yp0 = y0; yp1 = y1;
    }

    // logabsdet (match reference: log|prod over T| summed over D)
    out[(size_t)Btot * (T_STEPS * 2) + b] = logf(fabsf(p0)) + logf(fabsf(p1));
}

extern "C" void kernel_launch(void* const* d_in, const int* in_sizes, int n_in,
                              void* d_out, int out_size)
{
    const float* x    = (const float*)d_in[0];
    const float* z    = (const float*)d_in[1];
    const float* W_ih = (const float*)d_in[2];
    const float* W_hh = (const float*)d_in[3];
    const float* b_ih = (const float*)d_in[4];
    const float* b_hh = (const float*)d_in[5];
    const float* W1   = (const float*)d_in[6];
    const float* b1   = (const float*)d_in[7];
    const float* W2   = (const float*)d_in[8];
    const float* b2   = (const float*)d_in[9];

    int B = in_sizes[1] / 64;   // z is (B, 64)

    cudaFuncSetAttribute(flow_kernel, cudaFuncAttributeMaxDynamicSharedMemorySize, SMEM_BYTES);

    flow_kernel<<<B / BLK, BLK, SMEM_BYTES>>>(
        x, z, W_ih, W_hh, b_ih, b_hh, W1, b1, W2, b2, (float*)d_out, B);
}

// round 5
// speedup vs baseline: 1.3831x; 1.3831x over previous
#include <cuda_runtime.h>

#define T_STEPS 16
#define BLK 256
#define EPB 512            // batch elements per block (2 per thread)

using ull = unsigned long long;

union F2u { ull u; float2 f; };

__device__ __forceinline__ ull fma2(ull a, ull b, ull c) {
    ull d;
    asm("fma.rn.f32x2 %0, %1, %2, %3;" : "=l"(d) : "l"(a), "l"(b), "l"(c));
    return d;
}
__device__ __forceinline__ float hsum2(ull a, ull b) {
    ull s;
    asm("add.rn.f32x2 %0, %1, %2;" : "=l"(s) : "l"(a), "l"(b));
    F2u x; x.u = s;
    return x.f.x + x.f.y;
}

__device__ __forceinline__ float sigm(float x) {
    return __fdividef(1.0f, 1.0f + __expf(-x));
}
__device__ __forceinline__ float tanh_fast(float x) {
    float ax = fabsf(x);
    float e = __expf(-2.0f * ax);
    float t = __fdividef(1.0f - e, 1.0f + e);
    return copysignf(t, x);
}
__device__ __forceinline__ float softplus_(float x) {
    return fmaxf(x, 0.0f) + log1pf(__expf(-fabsf(x)));
}

// shared-memory float offsets
#define OFF_WHH 0        // 12288  (192 x 64, row-major)
#define OFF_W1T 12288    // 2048   (transposed: [m*64+k])
#define OFF_GIW 14336    // 192 x float4 {wih0, wih1, bias(.z), bhh_n(.w)} = 768 floats
#define OFF_B1  15104    // 32
#define OFF_W2  15136    // 128    (32 x 4 row-major -> float4 per row)
#define OFF_B2  15264    // 4
#define WEIGHT_BYTES (15268 * 4)                  // 61072, 16B-aligned
#define SMEM_BYTES (WEIGHT_BYTES + 32 * EPB * 8)  // + hbuf (ull[32][EPB]) = 192144

__global__ void __launch_bounds__(BLK)
flow_kernel(const float* __restrict__ x, const float* __restrict__ z,
            const float* __restrict__ W_ih, const float* __restrict__ W_hh,
            const float* __restrict__ b_ih, const float* __restrict__ b_hh,
            const float* __restrict__ W1, const float* __restrict__ b1,
            const float* __restrict__ W2, const float* __restrict__ b2,
            float* __restrict__ out, int Btot)
{
    extern __shared__ unsigned char smem_raw[];
    float* sw = (float*)smem_raw;
    const int tid = threadIdx.x;

    // ---- stage weights into shared ----
    for (int i = tid; i < 12288; i += BLK) sw[OFF_WHH + i] = W_hh[i];
    for (int i = tid; i < 2048; i += BLK) {         // transpose W1 (64x32) -> [m][k]
        int m = i >> 6, k = i & 63;
        sw[OFF_W1T + i] = W1[k * 32 + m];
    }
    for (int j = tid; j < 192; j += BLK) {          // giw: wih pair + biases
        float bi = b_ih[j], bh = b_hh[j];
        float4 v;
        if (j < 128) v = make_float4(W_ih[2 * j], W_ih[2 * j + 1], bi + bh, 0.0f);
        else         v = make_float4(W_ih[2 * j], W_ih[2 * j + 1], bi, bh);
        *(float4*)(sw + OFF_GIW + j * 4) = v;
    }
    for (int i = tid; i < 128; i += BLK) sw[OFF_W2 + i] = W2[i];
    if (tid < 32) sw[OFF_B1 + tid] = b1[tid];
    if (tid < 4)  sw[OFF_B2 + tid] = b2[tid];
    __syncthreads();

    ull* hbuf = (ull*)(smem_raw + WEIGHT_BYTES);   // [32][EPB] per-element h scratch

    const int b0 = blockIdx.x * EPB + tid;          // element A
    const int b1i = b0 + BLK;                       // element B

    // h = z for both elements (packed pairs in registers + smem scratch copy)
    ull ha[32], hb[32];
    const ull* za = (const ull*)(z + (size_t)b0 * 64);
    const ull* zbv = (const ull*)(z + (size_t)b1i * 64);
    #pragma unroll
    for (int k = 0; k < 32; ++k) {
        ha[k] = za[k];  hbuf[k * EPB + tid] = ha[k];
        hb[k] = zbv[k]; hbuf[k * EPB + BLK + tid] = hb[k];
    }

    const float2* xA = (const float2*)(x + (size_t)b0  * (T_STEPS * 2));
    const float2* xB = (const float2*)(x + (size_t)b1i * (T_STEPS * 2));
    float2*       yA = (float2*)(out + (size_t)b0  * (T_STEPS * 2));
    float2*       yB = (float2*)(out + (size_t)b1i * (T_STEPS * 2));

    const ulonglong2* whh2 = (const ulonglong2*)(sw + OFF_WHH);  // row j at j*16
    const float4* giw = (const float4*)(sw + OFF_GIW);
    const ulonglong2* w1t2 = (const ulonglong2*)(sw + OFF_W1T);  // row m at m*16
    const float4* w2v = (const float4*)(sw + OFF_W2);
    const float* b1s = sw + OFF_B1;
    const float* b2s = sw + OFF_B2;
    const float bb20 = b2s[0], bb21 = b2s[1], bb22 = b2s[2], bb23 = b2s[3];

    float yA0 = 0.f, yA1 = 0.f, yB0 = 0.f, yB1 = 0.f;   // y_{t-1}
    float pA0 = 1.f, pA1 = 1.f, pB0 = 1.f, pB1 = 1.f;   // running scale products

    #pragma unroll 1
    for (int t = 0; t < T_STEPS; ++t) {
        float2 xa = xA[t];
        float2 xbv = xB[t];

        // ---- GRU: gh = h @ W_hh^T (+ biases), fused gates, both elements ----
        #pragma unroll 1
        for (int j = 0; j < 64; ++j) {
            const ulonglong2* wr = whh2 + j * 16;
            const ulonglong2* wzp = wr + 1024;   // row 64+j
            const ulonglong2* wn = wr + 2048;    // row 128+j
            ull arA0 = 0, arA1 = 0, azA0 = 0, azA1 = 0, anA0 = 0, anA1 = 0;
            ull arB0 = 0, arB1 = 0, azB0 = 0, azB1 = 0, anB0 = 0, anB1 = 0;
            #pragma unroll
            for (int kk = 0; kk < 16; ++kk) {
                ulonglong2 wa = wr[kk];
                arA0 = fma2(ha[2 * kk], wa.x, arA0); arA1 = fma2(ha[2 * kk + 1], wa.y, arA1);
                arB0 = fma2(hb[2 * kk], wa.x, arB0); arB1 = fma2(hb[2 * kk + 1], wa.y, arB1);
                ulonglong2 wb = wzp[kk];
                azA0 = fma2(ha[2 * kk], wb.x, azA0); azA1 = fma2(ha[2 * kk + 1], wb.y, azA1);
                azB0 = fma2(hb[2 * kk], wb.x, azB0); azB1 = fma2(hb[2 * kk + 1], wb.y, azB1);
                ulonglong2 wc = wn[kk];
                anA0 = fma2(ha[2 * kk], wc.x, anA0); anA1 = fma2(ha[2 * kk + 1], wc.y, anA1);
                anB0 = fma2(hb[2 * kk], wc.x, anB0); anB1 = fma2(hb[2 * kk + 1], wc.y, anB1);
            }
            float4 wgr = giw[j];
            float4 wgz = giw[64 + j];
            float4 wgn = giw[128 + j];
            float* hsA = (float*)(hbuf + (j >> 1) * EPB + tid);
            float* hsB = (float*)(hbuf + (j >> 1) * EPB + BLK + tid);

            // element A
            {
                float hr = hsum2(arA0, arA1);
                float hz = hsum2(azA0, azA1);
                float hn = hsum2(anA0, anA1) + wgn.w;
                float r = sigm(fmaf(yA1, wgr.y, fmaf(yA0, wgr.x, wgr.z)) + hr);
                float u = sigm(fmaf(yA1, wgz.y, fmaf(yA0, wgz.x, wgz.z)) + hz);
                float gn = fmaf(yA1, wgn.y, fmaf(yA0, wgn.x, wgn.z));
                float n = tanh_fast(fmaf(r, hn, gn));
                float hold = hsA[j & 1];
                hsA[j & 1] = fmaf(u, hold - n, n);
            }
            // element B
            {
                float hr = hsum2(arB0, arB1);
                float hz = hsum2(azB0, azB1);
                float hn = hsum2(anB0, anB1) + wgn.w;
                float r = sigm(fmaf(yB1, wgr.y, fmaf(yB0, wgr.x, wgr.z)) + hr);
                float u = sigm(fmaf(yB1, wgz.y, fmaf(yB0, wgz.x, wgz.z)) + hz);
                float gn = fmaf(yB1, wgn.y, fmaf(yB0, wgn.x, wgn.z));
                float n = tanh_fast(fmaf(r, hn, gn));
                float hold = hsB[j & 1];
                hsB[j & 1] = fmaf(u, hold - n, n);
            }
        }

        // reload h (now h_new) into registers
        #pragma unroll
        for (int k = 0; k < 32; ++k) {
            ha[k] = hbuf[k * EPB + tid];
            hb[k] = hbuf[k * EPB + BLK + tid];
        }

        // ---- MLP: ls = relu(h@W1 + b1) @ W2 + b2, both elements share weight loads ----
        float lsA0 = bb20, lsA1 = bb21, lsA2 = bb22, lsA3 = bb23;
        float lsB0 = bb20, lsB1 = bb21, lsB2 = bb22, lsB3 = bb23;
        #pragma unroll 1
        for (int m = 0; m < 32; ++m) {
            const ulonglong2* wm = w1t2 + m * 16;
            ull aA0 = 0, aA1 = 0, aB0 = 0, aB1 = 0;
            #pragma unroll
            for (int kk = 0; kk < 16; ++kk) {
                ulonglong2 w = wm[kk];
                aA0 = fma2(ha[2 * kk], w.x, aA0);
                aA1 = fma2(ha[2 * kk + 1], w.y, aA1);
                aB0 = fma2(hb[2 * kk], w.x, aB0);
                aB1 = fma2(hb[2 * kk + 1], w.y, aB1);
            }
            float hidA = fmaxf(hsum2(aA0, aA1) + b1s[m], 0.0f);
            float hidB = fmaxf(hsum2(aB0, aB1) + b1s[m], 0.0f);
            float4 wv = w2v[m];
            lsA0 = fmaf(hidA, wv.x, lsA0);
            lsA1 = fmaf(hidA, wv.y, lsA1);
            lsA2 = fmaf(hidA, wv.z, lsA2);
            lsA3 = fmaf(hidA, wv.w, lsA3);
            lsB0 = fmaf(hidB, wv.x, lsB0);
            lsB1 = fmaf(hidB, wv.y, lsB1);
            lsB2 = fmaf(hidB, wv.z, lsB2);
            lsB3 = fmaf(hidB, wv.w, lsB3);
        }

        // element A head
        {
            float s0 = softplus_(lsA2) + 0.001f;
            float s1 = softplus_(lsA3) + 0.001f;
            float y0 = yA0 + lsA0 + s0 * xa.x;
            float y1 = yA1 + lsA1 + s1 * xa.y;
            yA[t] = make_float2(y0, y1);
            pA0 *= s0; pA1 *= s1;
            yA0 = y0; yA1 = y1;
        }
        // element B head
        {
            float s0 = softplus_(lsB2) + 0.001f;
            float s1 = softplus_(lsB3) + 0.001f;
            float y0 = yB0 + lsB0 + s0 * xbv.x;
            float y1 = yB1 + lsB1 + s1 * xbv.y;
            yB[t] = make_float2(y0, y1);
            pB0 *= s0; pB1 *= s1;
            yB0 = y0; yB1 = y1;
        }
    }

    // logabsdet (match reference: log|prod over T| summed over D)
    out[(size_t)Btot * (T_STEPS * 2) + b0]  = logf(fabsf(pA0)) + logf(fabsf(pA1));
    out[(size_t)Btot * (T_STEPS * 2) + b1i] = logf(fabsf(pB0)) + logf(fabsf(pB1));
}

extern "C" void kernel_launch(void* const* d_in, const int* in_sizes, int n_in,
                              void* d_out, int out_size)
{
    const float* x    = (const float*)d_in[0];
    const float* z    = (const float*)d_in[1];
    const float* W_ih = (const float*)d_in[2];
    const float* W_hh = (const float*)d_in[3];
    const float* b_ih = (const float*)d_in[4];
    const float* b_hh = (const float*)d_in[5];
    const float* W1   = (const float*)d_in[6];
    const float* b1   = (const float*)d_in[7];
    const float* W2   = (const float*)d_in[8];
    const float* b2   = (const float*)d_in[9];

    int B = in_sizes[1] / 64;   // z is (B, 64)

    cudaFuncSetAttribute(flow_kernel, cudaFuncAttributeMaxDynamicSharedMemorySize, SMEM_BYTES);

    flow_kernel<<<B / EPB, BLK, SMEM_BYTES>>>(
        x, z, W_ih, W_hh, b_ih, b_hh, W1, b1, W2, b2, (float*)d_out, B);
}

// round 6
// speedup vs baseline: 1.4578x; 1.0540x over previous
#include <cuda_runtime.h>

#define T_STEPS 16
#define BLK 224
#define EPB 448            // batch elements per block (2 per thread)

using ull = unsigned long long;

union F2u { ull u; float2 f; };

__device__ __forceinline__ ull fma2(ull a, ull b, ull c) {
    ull d;
    asm("fma.rn.f32x2 %0, %1, %2, %3;" : "=l"(d) : "l"(a), "l"(b), "l"(c));
    return d;
}
__device__ __forceinline__ float hsum2(ull a, ull b) {
    ull s;
    asm("add.rn.f32x2 %0, %1, %2;" : "=l"(s) : "l"(a), "l"(b));
    F2u x; x.u = s;
    return x.f.x + x.f.y;
}

__device__ __forceinline__ float tanh_ap(float x) {
    float y; asm("tanh.approx.f32 %0, %1;" : "=f"(y) : "f"(x)); return y;
}
__device__ __forceinline__ float sigm(float x) {
    return fmaf(tanh_ap(0.5f * x), 0.5f, 0.5f);
}
__device__ __forceinline__ float softplus_(float x) {
    return fmaxf(x, 0.0f) + log1pf(__expf(-fabsf(x)));   // exact: sets rel_err
}

// shared-memory float offsets
#define OFF_WHH 0        // 12288  (192 x 64, row-major)
#define OFF_W1T 12288    // 2048   (transposed: [m*64+k])
#define OFF_GIW 14336    // 192 x float4 {wih0, wih1, bias(.z), bhh_n(.w)} = 768 floats
#define OFF_B1  15104    // 32
#define OFF_W2  15136    // 128    (32 x 4 row-major -> float4 per row)
#define OFF_B2  15264    // 4
#define WEIGHT_BYTES (15268 * 4)                  // 61072, 16B-aligned
#define SMEM_BYTES (WEIGHT_BYTES + 32 * EPB * 8)  // + hbuf (ull[32][EPB]) = 175760

__global__ void __launch_bounds__(BLK)
flow_kernel(const float* __restrict__ x, const float* __restrict__ z,
            const float* __restrict__ W_ih, const float* __restrict__ W_hh,
            const float* __restrict__ b_ih, const float* __restrict__ b_hh,
            const float* __restrict__ W1, const float* __restrict__ b1,
            const float* __restrict__ W2, const float* __restrict__ b2,
            float* __restrict__ out, int Btot)
{
    extern __shared__ unsigned char smem_raw[];
    float* sw = (float*)smem_raw;
    const int tid = threadIdx.x;

    // ---- stage weights into shared ----
    for (int i = tid; i < 12288; i += BLK) sw[OFF_WHH + i] = W_hh[i];
    for (int i = tid; i < 2048; i += BLK) {         // transpose W1 (64x32) -> [m][k]
        int m = i >> 6, k = i & 63;
        sw[OFF_W1T + i] = W1[k * 32 + m];
    }
    for (int j = tid; j < 192; j += BLK) {          // giw: wih pair + biases
        float bi = b_ih[j], bh = b_hh[j];
        float4 v;
        if (j < 128) v = make_float4(W_ih[2 * j], W_ih[2 * j + 1], bi + bh, 0.0f);
        else         v = make_float4(W_ih[2 * j], W_ih[2 * j + 1], bi, bh);
        *(float4*)(sw + OFF_GIW + j * 4) = v;
    }
    for (int i = tid; i < 128; i += BLK) sw[OFF_W2 + i] = W2[i];
    if (tid < 32) sw[OFF_B1 + tid] = b1[tid];
    if (tid < 4)  sw[OFF_B2 + tid] = b2[tid];
    __syncthreads();

    ull* hbuf = (ull*)(smem_raw + WEIGHT_BYTES);   // [32][EPB] per-element h scratch

    const int b0 = blockIdx.x * EPB + tid;          // element A (always valid: grid sized so)
    const int b1r = b0 + BLK;                       // element B (may exceed Btot in last block)
    const bool vB = (b1r < Btot);
    const int b1i = vB ? b1r : b0;                  // clamp for loads

    // h = z for both elements (packed pairs in registers + smem scratch copy)
    ull ha[32], hb[32];
    const ull* za = (const ull*)(z + (size_t)b0 * 64);
    const ull* zbv = (const ull*)(z + (size_t)b1i * 64);
    #pragma unroll
    for (int k = 0; k < 32; ++k) {
        ha[k] = za[k];  hbuf[k * EPB + tid] = ha[k];
        hb[k] = zbv[k]; hbuf[k * EPB + BLK + tid] = hb[k];
    }

    const float2* xA = (const float2*)(x + (size_t)b0  * (T_STEPS * 2));
    const float2* xB = (const float2*)(x + (size_t)b1i * (T_STEPS * 2));
    float2*       yA = (float2*)(out + (size_t)b0  * (T_STEPS * 2));
    float2*       yB = (float2*)(out + (size_t)b1r * (T_STEPS * 2));

    const ulonglong2* whh2 = (const ulonglong2*)(sw + OFF_WHH);  // row j at j*16
    const float4* giw = (const float4*)(sw + OFF_GIW);
    const ulonglong2* w1t2 = (const ulonglong2*)(sw + OFF_W1T);  // row m at m*16
    const float4* w2v = (const float4*)(sw + OFF_W2);
    const float* b1s = sw + OFF_B1;
    const float* b2s = sw + OFF_B2;
    const float bb20 = b2s[0], bb21 = b2s[1], bb22 = b2s[2], bb23 = b2s[3];

    float yA0 = 0.f, yA1 = 0.f, yB0 = 0.f, yB1 = 0.f;   // y_{t-1}
    float pA0 = 1.f, pA1 = 1.f, pB0 = 1.f, pB1 = 1.f;   // running scale products

    #pragma unroll 1
    for (int t = 0; t < T_STEPS; ++t) {
        float2 xa = xA[t];
        float2 xbv = xB[t];

        // ---- GRU: gh = h @ W_hh^T (+ biases), fused gates, both elements ----
        #pragma unroll 1
        for (int j = 0; j < 64; ++j) {
            const ulonglong2* wr = whh2 + j * 16;
            const ulonglong2* wzp = wr + 1024;   // row 64+j
            const ulonglong2* wn = wr + 2048;    // row 128+j
            ull arA0 = 0, arA1 = 0, azA0 = 0, azA1 = 0, anA0 = 0, anA1 = 0;
            ull arB0 = 0, arB1 = 0, azB0 = 0, azB1 = 0, anB0 = 0, anB1 = 0;
            #pragma unroll
            for (int kk = 0; kk < 16; ++kk) {
                ulonglong2 wa = wr[kk];
                arA0 = fma2(ha[2 * kk], wa.x, arA0); arA1 = fma2(ha[2 * kk + 1], wa.y, arA1);
                arB0 = fma2(hb[2 * kk], wa.x, arB0); arB1 = fma2(hb[2 * kk + 1], wa.y, arB1);
                ulonglong2 wb = wzp[kk];
                azA0 = fma2(ha[2 * kk], wb.x, azA0); azA1 = fma2(ha[2 * kk + 1], wb.y, azA1);
                azB0 = fma2(hb[2 * kk], wb.x, azB0); azB1 = fma2(hb[2 * kk + 1], wb.y, azB1);
                ulonglong2 wc = wn[kk];
                anA0 = fma2(ha[2 * kk], wc.x, anA0); anA1 = fma2(ha[2 * kk + 1], wc.y, anA1);
                anB0 = fma2(hb[2 * kk], wc.x, anB0); anB1 = fma2(hb[2 * kk + 1], wc.y, anB1);
            }
            float4 wgr = giw[j];
            float4 wgz = giw[64 + j];
            float4 wgn = giw[128 + j];
            float* hsA = (float*)(hbuf + (j >> 1) * EPB + tid);
            float* hsB = (float*)(hbuf + (j >> 1) * EPB + BLK + tid);

            // element A
            {
                float hr = hsum2(arA0, arA1);
                float hz = hsum2(azA0, azA1);
                float hn = hsum2(anA0, anA1) + wgn.w;
                float r = sigm(fmaf(yA1, wgr.y, fmaf(yA0, wgr.x, wgr.z)) + hr);
                float u = sigm(fmaf(yA1, wgz.y, fmaf(yA0, wgz.x, wgz.z)) + hz);
                float gn = fmaf(yA1, wgn.y, fmaf(yA0, wgn.x, wgn.z));
                float n = tanh_ap(fmaf(r, hn, gn));
                float hold = hsA[j & 1];
                hsA[j & 1] = fmaf(u, hold - n, n);
            }
            // element B
            {
                float hr = hsum2(arB0, arB1);
                float hz = hsum2(azB0, azB1);
                float hn = hsum2(anB0, anB1) + wgn.w;
                float r = sigm(fmaf(yB1, wgr.y, fmaf(yB0, wgr.x, wgr.z)) + hr);
                float u = sigm(fmaf(yB1, wgz.y, fmaf(yB0, wgz.x, wgz.z)) + hz);
                float gn = fmaf(yB1, wgn.y, fmaf(yB0, wgn.x, wgn.z));
                float n = tanh_ap(fmaf(r, hn, gn));
                float hold = hsB[j & 1];
                hsB[j & 1] = fmaf(u, hold - n, n);
            }
        }

        // reload h (now h_new) into registers
        #pragma unroll
        for (int k = 0; k < 32; ++k) {
            ha[k] = hbuf[k * EPB + tid];
            hb[k] = hbuf[k * EPB + BLK + tid];
        }

        // ---- MLP: ls = relu(h@W1 + b1) @ W2 + b2, both elements share weight loads ----
        float lsA0 = bb20, lsA1 = bb21, lsA2 = bb22, lsA3 = bb23;
        float lsB0 = bb20, lsB1 = bb21, lsB2 = bb22, lsB3 = bb23;
        #pragma unroll 1
        for (int m = 0; m < 32; ++m) {
            const ulonglong2* wm = w1t2 + m * 16;
            ull aA0 = 0, aA1 = 0, aB0 = 0, aB1 = 0;
            #pragma unroll
            for (int kk = 0; kk < 16; ++kk) {
                ulonglong2 w = wm[kk];
                aA0 = fma2(ha[2 * kk], w.x, aA0);
                aA1 = fma2(ha[2 * kk + 1], w.y, aA1);
                aB0 = fma2(hb[2 * kk], w.x, aB0);
                aB1 = fma2(hb[2 * kk + 1], w.y, aB1);
            }
            float hidA = fmaxf(hsum2(aA0, aA1) + b1s[m], 0.0f);
            float hidB = fmaxf(hsum2(aB0, aB1) + b1s[m], 0.0f);
            float4 wv = w2v[m];
            lsA0 = fmaf(hidA, wv.x, lsA0);
            lsA1 = fmaf(hidA, wv.y, lsA1);
            lsA2 = fmaf(hidA, wv.z, lsA2);
            lsA3 = fmaf(hidA, wv.w, lsA3);
            lsB0 = fmaf(hidB, wv.x, lsB0);
            lsB1 = fmaf(hidB, wv.y, lsB1);
            lsB2 = fmaf(hidB, wv.z, lsB2);
            lsB3 = fmaf(hidB, wv.w, lsB3);
        }

        // element A head
        {
            float s0 = softplus_(lsA2) + 0.001f;
            float s1 = softplus_(lsA3) + 0.001f;
            float y0 = yA0 + lsA0 + s0 * xa.x;
            float y1 = yA1 + lsA1 + s1 * xa.y;
            yA[t] = make_float2(y0, y1);
            pA0 *= s0; pA1 *= s1;
            yA0 = y0; yA1 = y1;
        }
        // element B head
        {
            float s0 = softplus_(lsB2) + 0.001f;
            float s1 = softplus_(lsB3) + 0.001f;
            float y0 = yB0 + lsB0 + s0 * xbv.x;
            float y1 = yB1 + lsB1 + s1 * xbv.y;
            if (vB) yB[t] = make_float2(y0, y1);
            pB0 *= s0; pB1 *= s1;
            yB0 = y0; yB1 = y1;
        }
    }

    // logabsdet (match reference: log|prod over T| summed over D)
    out[(size_t)Btot * (T_STEPS * 2) + b0] = logf(fabsf(pA0)) + logf(fabsf(pA1));
    if (vB)
        out[(size_t)Btot * (T_STEPS * 2) + b1r] = logf(fabsf(pB0)) + logf(fabsf(pB1));
}

extern "C" void kernel_launch(void* const* d_in, const int* in_sizes, int n_in,
                              void* d_out, int out_size)
{
    const float* x    = (const float*)d_in[0];
    const float* z    = (const float*)d_in[1];
    const float* W_ih = (const float*)d_in[2];
    const float* W_hh = (const float*)d_in[3];
    const float* b_ih = (const float*)d_in[4];
    const float* b_hh = (const float*)d_in[5];
    const float* W1   = (const float*)d_in[6];
    const float* b1   = (const float*)d_in[7];
    const float* W2   = (const float*)d_in[8];
    const float* b2   = (const float*)d_in[9];

    int B = in_sizes[1] / 64;   // z is (B, 64)
    int grid = (B + EPB - 1) / EPB;   // 293 for B=131072 -> waves 148+145 (99% balance)

    cudaFuncSetAttribute(flow_kernel, cudaFuncAttributeMaxDynamicSharedMemorySize, SMEM_BYTES);

    flow_kernel<<<grid, BLK, SMEM_BYTES>>>(
        x, z, W_ih, W_hh, b_ih, b_hh, W1, b1, W2, b2, (float*)d_out, B);
}